// round 15
// baseline (speedup 1.0000x reference)
#include <cuda_runtime.h>

// Sinkhorn distance, N=M=4096, D=2, P=1, eps=0.1, 50 iterations.
// Round-14 math (packed f32x2 + MUFU ex2, log2 domain) with 2 CTAs/SM:
// 256 CTAs x 512 threads, __launch_bounds__(512,2). While one CTA sits in
// its reduce/barrier tail, the co-resident CTA keeps the MUFU pipe fed.
// CTA owns 16 rows; lane = (row, j-sub): row = lane&15, sub = lane>>4.

#define NN      4096
#define NCTA    256
#define NT      512
#define NWARP   16
#define RPC     16          // rows per CTA
#define ITERS   50

#define SCALEF      14.426950408889634f    // log2(e)/eps
#define INV_SCALEF  0.06931471805599453f   // eps*ln(2)
#define LMU2        (-11.9999409054f)      // log2(1/4096 + 1e-8)

typedef unsigned long long ull;

__device__ __align__(256) float g_u[NN];
__device__ __align__(256) float g_v[NN];
__device__ float g_cost[NCTA];
__device__ unsigned int g_costcnt;
__device__ unsigned int sk_bar_count;
__device__ volatile unsigned int sk_bar_phase;

__device__ __forceinline__ float ex2f(float v) {
    float r; asm("ex2.approx.f32 %0, %1;" : "=f"(r) : "f"(v)); return r;
}
__device__ __forceinline__ float lg2f(float v) {
    float r; asm("lg2.approx.f32 %0, %1;" : "=f"(r) : "f"(v)); return r;
}
__device__ __forceinline__ ull fadd2(ull a, ull b) {
    ull r; asm("add.rn.f32x2 %0, %1, %2;" : "=l"(r) : "l"(a), "l"(b)); return r;
}
__device__ __forceinline__ ull pk(float lo, float hi) {
    ull r; asm("mov.b64 %0, {%1, %2};" : "=l"(r) : "f"(lo), "f"(hi)); return r;
}
__device__ __forceinline__ void upk(ull v, float& lo, float& hi) {
    asm("mov.b64 {%0, %1}, %2;" : "=f"(lo), "=f"(hi) : "l"(v));
}

// Proven barrier: atomicAdd arrival, tid0 spins on one volatile word.
__device__ __forceinline__ void grid_barrier(unsigned int target) {
    __threadfence();
    __syncthreads();
    if (threadIdx.x == 0) {
        unsigned int t = atomicAdd(&sk_bar_count, 1u);
        if (t == NCTA - 1) {
            sk_bar_count = 0;
            __threadfence();
            sk_bar_phase = target;
        } else {
            while (sk_bar_phase < target) { }
        }
    }
    __syncthreads();
}

__global__ void sk_init_kernel() {
    int t = blockIdx.x * blockDim.x + threadIdx.x;
    if (t == 0) { sk_bar_count = 0; sk_bar_phase = 0; g_costcnt = 0; }
    for (int i = t; i < NN; i += gridDim.x * blockDim.x) g_v[i] = 0.f;
}

// acc += 2^{v - |X0-y0| - |X1-y1|} for a point pair (packed f32x2).
__device__ __forceinline__ void sk_step(ull& acc, float4 c, float vl, float vh,
                                        ull X0p, ull X1p) {
    ull d0 = fadd2(X0p, pk(c.x, c.y));
    ull d1 = fadd2(X1p, pk(c.z, c.w));
    float d0l, d0h, d1l, d1h;
    upk(d0, d0l, d0h);
    upk(d1, d1l, d1h);
    float sl = -fabsf(d0l) - fabsf(d1l);
    float sh = -fabsf(d0h) - fabsf(d1h);
    ull arg = fadd2(pk(vl, vh), pk(sl, sh));
    float al, ah;
    upk(arg, al, ah);
    acc = fadd2(acc, pk(ex2f(al), ex2f(ah)));
}

// 64 pairs: cb = 64 coord float4s, vb4 = 32 v float4s (this lane's slice).
__device__ __forceinline__ float chunk_sum(const float4* __restrict__ cb,
                                           const float4* __restrict__ vb4,
                                           ull X0p, ull X1p) {
    ull a0 = 0, a1 = 0, a2 = 0, a3 = 0;
    #pragma unroll 4
    for (int k = 0; k < 32; k += 2) {
        float4 c0 = cb[2 * k + 0];
        float4 c1 = cb[2 * k + 1];
        float4 v0 = vb4[k];
        sk_step(a0, c0, v0.x, v0.y, X0p, X1p);
        sk_step(a1, c1, v0.z, v0.w, X0p, X1p);
        float4 c2 = cb[2 * k + 2];
        float4 c3 = cb[2 * k + 3];
        float4 v1 = vb4[k + 1];
        sk_step(a2, c2, v1.x, v1.y, X0p, X1p);
        sk_step(a3, c3, v1.z, v1.w, X0p, X1p);
    }
    ull t = fadd2(fadd2(a0, a1), fadd2(a2, a3));
    float tl, th;
    upk(t, tl, th);
    return tl + th;
}

__global__ void __launch_bounds__(NT, 2)
sk_persist_kernel(const float* __restrict__ x, const float* __restrict__ y,
                  float* __restrict__ out) {
    extern __shared__ float4 smem_raw[];
    float4* sxc = smem_raw;                 // 32KB {-x0a,-x0b,-x1a,-x1b} pair-interleaved
    float4* syc = smem_raw + NN / 2;        // 32KB
    float*  sv  = (float*)(smem_raw + NN);  // 16KB
    __shared__ float part[NWARP * 33];
    __shared__ float suRow[RPC];
    __shared__ float red[NWARP];

    const int tid  = threadIdx.x;
    const int lane = tid & 31;
    const int wid  = tid >> 5;               // 0..15
    const int sub  = lane >> 4;              // 0..1  (j sub-chunk)
    const int lrow = lane & 15;              // 0..15 (row within CTA)
    const int cta  = blockIdx.x;
    const int rbase = cta * RPC;

    // Prologue: negated, pre-scaled coords (immutable).
    for (int p = tid; p < NN / 2; p += NT) {
        float4 r = ((const float4*)x)[p];
        sxc[p] = make_float4(-SCALEF * r.x, -SCALEF * r.z, -SCALEF * r.y, -SCALEF * r.w);
        float4 q = ((const float4*)y)[p];
        syc[p] = make_float4(-SCALEF * q.x, -SCALEF * q.z, -SCALEF * q.y, -SCALEF * q.w);
    }
    __syncthreads();

    const int myrow = rbase + lrow;
    const float X0 = x[2 * myrow] * SCALEF;
    const float X1 = x[2 * myrow + 1] * SCALEF;
    const float Y0 = y[2 * myrow] * SCALEF;
    const float Y1 = y[2 * myrow + 1] * SCALEF;
    const ull X0p = pk(X0, X0), X1p = pk(X1, X1);
    const ull Y0p = pk(Y0, Y0), Y1p = pk(Y1, Y1);

    // Per-warp j-slice bases. Warp wid covers j in [wid*256, wid*256+256).
    const int stage0 = wid * 64 + lane;          // float4 stage slots (2 per lane)
    const int stage1 = wid * 64 + 32 + lane;
    const float4* cbU = syc + wid * 128 + sub * 64;   // u-pass coords
    const float4* cbV = sxc + wid * 128 + sub * 64;   // v-pass coords
    const int vb4off = wid * 64 + sub * 32;           // v/u slice float4 base

    unsigned int phase = 0;

    for (int it = 0; it < ITERS; ++it) {
        // ===== u pass: u_i = LMU2 - log2( sum_j 2^{v_j - C_ij} ) =====
        ((float4*)sv)[stage0] = __ldcg((const float4*)g_v + stage0);
        ((float4*)sv)[stage1] = __ldcg((const float4*)g_v + stage1);
        __syncwarp();
        part[wid * 33 + lane] = chunk_sum(cbU, (const float4*)sv + vb4off, X0p, X1p);
        __syncthreads();
        {   // warp `wid` reduces row rbase+wid: 32 partials (16 warps x 2 subs)
            float pv = part[(lane & 15) * 33 + wid + ((lane >> 4) << 4)];
            #pragma unroll
            for (int o = 16; o > 0; o >>= 1) pv += __shfl_xor_sync(0xffffffffu, pv, o);
            if (lane == 0) __stcg(&g_u[rbase + wid], LMU2 - lg2f(pv));
        }
        grid_barrier(++phase);

        // ===== v pass: v_j = LMU2 - log2( sum_i 2^{u_i - C_ij} ) =====
        ((float4*)sv)[stage0] = __ldcg((const float4*)g_u + stage0);
        ((float4*)sv)[stage1] = __ldcg((const float4*)g_u + stage1);
        __syncwarp();
        part[wid * 33 + lane] = chunk_sum(cbV, (const float4*)sv + vb4off, Y0p, Y1p);
        __syncthreads();
        {
            float pv = part[(lane & 15) * 33 + wid + ((lane >> 4) << 4)];
            #pragma unroll
            for (int o = 16; o > 0; o >>= 1) pv += __shfl_xor_sync(0xffffffffu, pv, o);
            if (lane == 0) __stcg(&g_v[rbase + wid], LMU2 - lg2f(pv));
        }
        grid_barrier(++phase);
    }

    // ===== final: pi = 2^{u_i + v_j - C_ij}, C, cost = sum(pi*C) =====
    for (int q = tid; q < NN / 4; q += NT)
        ((float4*)sv)[q] = __ldcg((const float4*)g_v + q);
    if (tid < RPC) suRow[tid] = __ldcg(&g_u[rbase + tid]);
    __syncthreads();

    const size_t NM = (size_t)NN * NN;
    float* pi_out = out + 1;
    float* c_out  = out + 1 + NM;

    float cacc = 0.f;
    for (int r = 0; r < RPC; ++r) {
        const int i = rbase + r;
        const float Xa = x[2 * i] * SCALEF;
        const float Xb = x[2 * i + 1] * SCALEF;
        const float ui = suRow[r];
        const size_t off = (size_t)i * NN;
        for (int q = tid; q < NN / 4; q += NT) {
            float4 ca = syc[2 * q];
            float4 cb = syc[2 * q + 1];
            float4 v4 = ((const float4*)sv)[q];
            float ct0 = fabsf(Xa + ca.x) + fabsf(Xb + ca.z);
            float ct1 = fabsf(Xa + ca.y) + fabsf(Xb + ca.w);
            float ct2 = fabsf(Xa + cb.x) + fabsf(Xb + cb.z);
            float ct3 = fabsf(Xa + cb.y) + fabsf(Xb + cb.w);
            float p0 = ex2f(ui + v4.x - ct0);
            float p1 = ex2f(ui + v4.y - ct1);
            float p2 = ex2f(ui + v4.z - ct2);
            float p3 = ex2f(ui + v4.w - ct3);
            float c0 = ct0 * INV_SCALEF, c1 = ct1 * INV_SCALEF;
            float c2 = ct2 * INV_SCALEF, c3 = ct3 * INV_SCALEF;
            const size_t b = off + 4 * (size_t)q;
            pi_out[b + 0] = p0; pi_out[b + 1] = p1; pi_out[b + 2] = p2; pi_out[b + 3] = p3;
            c_out[b + 0]  = c0; c_out[b + 1]  = c1; c_out[b + 2]  = c2; c_out[b + 3]  = c3;
            cacc += p0 * c0 + p1 * c1;
            cacc += p2 * c2 + p3 * c3;
        }
    }
    #pragma unroll
    for (int o = 16; o > 0; o >>= 1) cacc += __shfl_xor_sync(0xffffffffu, cacc, o);
    if (lane == 0) red[wid] = cacc;
    __syncthreads();
    if (wid == 0) {
        float s = (lane < NWARP) ? red[lane] : 0.f;
        #pragma unroll
        for (int o = 16; o > 0; o >>= 1) s += __shfl_xor_sync(0xffffffffu, s, o);
        if (lane == 0) {
            __stcg(&g_cost[cta], s);
            __threadfence();
            unsigned int old = atomicAdd(&g_costcnt, 1u);
            if (old == NCTA - 1) {          // last CTA: deterministic final sum
                __threadfence();
                float t = 0.f;
                for (int b = 0; b < NCTA; ++b) t += __ldcg(&g_cost[b]);
                out[0] = t;                 // cost ** (1/P), P = 1
            }
        }
    }
}

extern "C" void kernel_launch(void* const* d_in, const int* in_sizes, int n_in,
                              void* d_out, int out_size) {
    (void)in_sizes; (void)n_in; (void)out_size;
    const float* x = (const float*)d_in[0];
    const float* y = (const float*)d_in[1];
    float* out = (float*)d_out;

    const size_t smem = (size_t)NN * sizeof(float4) + NN * sizeof(float);   // 80KB
    cudaFuncSetAttribute(sk_persist_kernel,
                         cudaFuncAttributeMaxDynamicSharedMemorySize, (int)smem);

    sk_init_kernel<<<8, 512>>>();
    sk_persist_kernel<<<NCTA, NT, smem>>>(x, y, out);
}